// round 2
// baseline (speedup 1.0000x reference)
#include <cuda_runtime.h>
#include <cstdint>

// Problem constants
#define B_DIM   128
#define OUT_DIM 1024
#define IN_DIM  1024

// Scratch: s[o,k] = d + a * sigmoid(dx * (w - x0))  (4 MB, static device array)
__device__ float g_sig[OUT_DIM * IN_DIM];

// ---------------------------------------------------------------------------
// threefry2x32, key = (0, 42)  [jax.random.key(42)]
//   ks0 = 0, ks1 = 42, ks2 = 0 ^ 42 ^ 0x1BD11BDA = 0x1BD11BF0
// Partitionable random_bits: ctr = (i >> 32, i & 0xffffffff) = (0, i),
// bits = out0 ^ out1.
// ---------------------------------------------------------------------------
__device__ __forceinline__ uint32_t rotl32(uint32_t x, int r) {
    return __funnelshift_l(x, x, r);
}

__device__ __forceinline__ uint32_t threefry_bits_42(uint32_t i) {
    const uint32_t ks0 = 0u, ks1 = 42u, ks2 = 0x1BD11BF0u;
    uint32_t x0 = ks0;          // ctr_hi = 0
    uint32_t x1 = i + ks1;
#define TF_RND(r) do { x0 += x1; x1 = rotl32(x1, r); x1 ^= x0; } while (0)
    TF_RND(13); TF_RND(15); TF_RND(26); TF_RND(6);
    x0 += ks1; x1 += ks2 + 1u;
    TF_RND(17); TF_RND(29); TF_RND(16); TF_RND(24);
    x0 += ks2; x1 += ks0 + 2u;
    TF_RND(13); TF_RND(15); TF_RND(26); TF_RND(6);
    x0 += ks0; x1 += ks1 + 3u;
    TF_RND(17); TF_RND(29); TF_RND(16); TF_RND(24);
    x0 += ks1; x1 += ks2 + 4u;
    TF_RND(13); TF_RND(15); TF_RND(26); TF_RND(6);
    x0 += ks2; x1 += ks0 + 5u;
#undef TF_RND
    return x0 ^ x1;
}

// ---------------------------------------------------------------------------
// Kernel 1: precompute s[o,k] = d + a * sigmoid(dx * (w - x0))
// ---------------------------------------------------------------------------
__global__ void sls_sigmoid_kernel(const float* __restrict__ w,
                                   const float* __restrict__ x0,
                                   const float* __restrict__ dx,
                                   const float* __restrict__ a,
                                   const float* __restrict__ d) {
    int i = blockIdx.x * blockDim.x + threadIdx.x;
    if (i < OUT_DIM * IN_DIM) {
        float z  = dx[i] * (w[i] - x0[i]);
        float sg = 1.0f / (1.0f + __expf(-z) * 0.0f + expf(-z) * 1.0f);
        g_sig[i] = d[i] + a[i] * sg;
    }
}

// ---------------------------------------------------------------------------
// Kernel 2: one warp per (b, o); lane handles 32 k-values (coalesced).
// out[b,o] = count{ u_i < p_i } + bias[o], u_i from partitionable threefry.
// ---------------------------------------------------------------------------
__global__ void __launch_bounds__(256)
sls_main_kernel(const float* __restrict__ input,
                const float* __restrict__ bias,
                float* __restrict__ out) {
    int gtid = blockIdx.x * blockDim.x + threadIdx.x;
    int w    = gtid >> 5;            // warp id: 0 .. 128*1024-1
    int lane = gtid & 31;

    int o = w & (OUT_DIM - 1);       // 0..1023
    int b = w >> 10;                 // 0..127

    const float* __restrict__ srow = g_sig + o * IN_DIM;
    const float* __restrict__ irow = input + b * IN_DIM;

    // flattened index base for (b, o, 0): i = b*2^20 + o*2^10 + k
    uint32_t base = ((uint32_t)b << 20) + ((uint32_t)o << 10) + (uint32_t)lane;

    int cnt = 0;

#pragma unroll 4
    for (int j = 0; j < 32; j++) {
        int k = (j << 5) + lane;     // coalesced across lanes

        float p = fminf(fmaxf(irow[k] * srow[k], 0.0f), 1.0f);

        uint32_t bits = threefry_bits_42(base + ((uint32_t)j << 5));

        // JAX uniform: bitcast((bits >> 9) | 0x3f800000) - 1.0  in [0, 1)
        float u = __uint_as_float((bits >> 9) | 0x3f800000u) - 1.0f;

        cnt += (u < p) ? 1 : 0;
    }

    cnt = __reduce_add_sync(0xffffffffu, cnt);

    if (lane == 0) {
        out[b * OUT_DIM + o] = (float)cnt + bias[o];
    }
}

// ---------------------------------------------------------------------------
// kernel_launch
// Inputs (metadata order): input(128*1024), weight(1024*1024), bias(1024),
//                          x0, dx, a, d (each 1024*1024)
// Output: (128, 1024) float32
// ---------------------------------------------------------------------------
extern "C" void kernel_launch(void* const* d_in, const int* in_sizes, int n_in,
                              void* d_out, int out_size) {
    const float* input  = (const float*)d_in[0];
    const float* weight = (const float*)d_in[1];
    const float* bias   = (const float*)d_in[2];
    const float* x0     = (const float*)d_in[3];
    const float* dx     = (const float*)d_in[4];
    const float* a      = (const float*)d_in[5];
    const float* d      = (const float*)d_in[6];
    float* out          = (float*)d_out;

    // Kernel 1: sigmoid table (1M elements)
    {
        int threads = 256;
        int blocks  = (OUT_DIM * IN_DIM + threads - 1) / threads;
        sls_sigmoid_kernel<<<blocks, threads>>>(weight, x0, dx, a, d);
    }

    // Kernel 2: 128*1024 warps, 8 warps/block -> 16384 blocks
    {
        int threads = 256;
        int blocks  = (B_DIM * OUT_DIM * 32) / threads;  // 16384
        sls_main_kernel<<<blocks, threads>>>(input, bias, out);
    }
}